// round 1
// baseline (speedup 1.0000x reference)
#include <cuda_runtime.h>
#include <math.h>

// Problem constants
#define BB 8
#define SS 2048
#define DD 768
#define NR (BB * SS)   // 16384 rows

// ---------------------------------------------------------------------------
// Scratch (allocation-free: __device__ globals per harness rules)
// ---------------------------------------------------------------------------
__device__ float g_Q[(size_t)NR * DD];                 // 50.3 MB
__device__ float g_K[(size_t)NR * DD];                 // 50.3 MB
__device__ float g_V[(size_t)NR * DD];                 // 50.3 MB
__device__ float g_Scores[(size_t)BB * SS * SS];       // 134.2 MB
__device__ float g_O[(size_t)NR * DD];                 // 50.3 MB

// ---------------------------------------------------------------------------
// SGEMM NT: C[m,n] = scale * sum_k A[m,k] * B[n,k]  (+ bias[n] if HAS_BIAS)
// A: row-major [M,K], B: row-major [N,K] (torch Linear / Q@K^T form)
// Tiles: 128x128x8, 256 threads, 8x8 per-thread microtile.
// Requires: M%128==0, N%128==0, K%8==0 (true for all shapes here).
// ---------------------------------------------------------------------------
template <bool HAS_BIAS>
__global__ void __launch_bounds__(256) sgemm_nt(
    const float* __restrict__ A, const float* __restrict__ Bm,
    float* __restrict__ C, const float* __restrict__ bias,
    int M, int N, int K, float scale,
    size_t strideA, size_t strideB, size_t strideC)
{
    A  += (size_t)blockIdx.z * strideA;
    Bm += (size_t)blockIdx.z * strideB;
    C  += (size_t)blockIdx.z * strideC;

    __shared__ float As[8][128];
    __shared__ float Bs[8][128];

    const int tid = threadIdx.x;
    const int tx  = tid & 15;       // 0..15 -> n microtile
    const int ty  = tid >> 4;       // 0..15 -> m microtile
    const int m0  = blockIdx.y * 128;
    const int n0  = blockIdx.x * 128;

    // Tile loaders: 128 rows x 8 k-cols, one float4 per thread per operand.
    const int lrow = tid >> 1;          // 0..127
    const int lcol = (tid & 1) * 4;     // 0 or 4
    const float* Aptr = A  + (size_t)(m0 + lrow) * K + lcol;
    const float* Bptr = Bm + (size_t)(n0 + lrow) * K + lcol;

    float acc[8][8];
    #pragma unroll
    for (int i = 0; i < 8; i++)
        #pragma unroll
        for (int j = 0; j < 8; j++) acc[i][j] = 0.0f;

    for (int k0 = 0; k0 < K; k0 += 8) {
        const float4 av = *(const float4*)(Aptr + k0);
        const float4 bv = *(const float4*)(Bptr + k0);
        __syncthreads();   // previous compute done before overwriting smem
        As[lcol + 0][lrow] = av.x;
        As[lcol + 1][lrow] = av.y;
        As[lcol + 2][lrow] = av.z;
        As[lcol + 3][lrow] = av.w;
        Bs[lcol + 0][lrow] = bv.x;
        Bs[lcol + 1][lrow] = bv.y;
        Bs[lcol + 2][lrow] = bv.z;
        Bs[lcol + 3][lrow] = bv.w;
        __syncthreads();

        #pragma unroll
        for (int kk = 0; kk < 8; kk++) {
            float a[8], b[8];
            *(float4*)(a + 0) = *(const float4*)&As[kk][ty * 8 + 0];
            *(float4*)(a + 4) = *(const float4*)&As[kk][ty * 8 + 4];
            *(float4*)(b + 0) = *(const float4*)&Bs[kk][tx * 8 + 0];
            *(float4*)(b + 4) = *(const float4*)&Bs[kk][tx * 8 + 4];
            #pragma unroll
            for (int i = 0; i < 8; i++)
                #pragma unroll
                for (int j = 0; j < 8; j++)
                    acc[i][j] = fmaf(a[i], b[j], acc[i][j]);
        }
    }

    // Epilogue
    float bload[8];
    #pragma unroll
    for (int j = 0; j < 8; j++)
        bload[j] = HAS_BIAS ? bias[n0 + tx * 8 + j] : 0.0f;

    #pragma unroll
    for (int i = 0; i < 8; i++) {
        const int m = m0 + ty * 8 + i;
        float4 out0, out1;
        out0.x = acc[i][0] * scale + bload[0];
        out0.y = acc[i][1] * scale + bload[1];
        out0.z = acc[i][2] * scale + bload[2];
        out0.w = acc[i][3] * scale + bload[3];
        out1.x = acc[i][4] * scale + bload[4];
        out1.y = acc[i][5] * scale + bload[5];
        out1.z = acc[i][6] * scale + bload[6];
        out1.w = acc[i][7] * scale + bload[7];
        float* crow = C + (size_t)m * N + n0 + tx * 8;
        *(float4*)(crow + 0) = out0;
        *(float4*)(crow + 4) = out1;
    }
}

// ---------------------------------------------------------------------------
// SGEMM NN: C[m,n] = sum_k A[m,k] * B[k,n]   (alpha @ V form)
// A: row-major [M,K], B: row-major [K,N]
// ---------------------------------------------------------------------------
__global__ void __launch_bounds__(256) sgemm_nn(
    const float* __restrict__ A, const float* __restrict__ Bm,
    float* __restrict__ C,
    int M, int N, int K,
    size_t strideA, size_t strideB, size_t strideC)
{
    A  += (size_t)blockIdx.z * strideA;
    Bm += (size_t)blockIdx.z * strideB;
    C  += (size_t)blockIdx.z * strideC;

    __shared__ float As[8][128];
    __shared__ float Bs[8][128];

    const int tid = threadIdx.x;
    const int tx  = tid & 15;
    const int ty  = tid >> 4;
    const int m0  = blockIdx.y * 128;
    const int n0  = blockIdx.x * 128;

    // A loader (same as NT)
    const int larow = tid >> 1;
    const int lacol = (tid & 1) * 4;
    const float* Aptr = A + (size_t)(m0 + larow) * K + lacol;
    // B loader: 8 k-rows x 128 n-cols
    const int lbrow = tid >> 5;          // 0..7
    const int lbcol = (tid & 31) * 4;    // 0..124
    const float* Bptr = Bm + (size_t)lbrow * N + n0 + lbcol;

    float acc[8][8];
    #pragma unroll
    for (int i = 0; i < 8; i++)
        #pragma unroll
        for (int j = 0; j < 8; j++) acc[i][j] = 0.0f;

    for (int k0 = 0; k0 < K; k0 += 8) {
        const float4 av = *(const float4*)(Aptr + k0);
        const float4 bv = *(const float4*)(Bptr + (size_t)k0 * N);
        __syncthreads();
        As[lacol + 0][larow] = av.x;
        As[lacol + 1][larow] = av.y;
        As[lacol + 2][larow] = av.z;
        As[lacol + 3][larow] = av.w;
        *(float4*)&Bs[lbrow][lbcol] = bv;
        __syncthreads();

        #pragma unroll
        for (int kk = 0; kk < 8; kk++) {
            float a[8], b[8];
            *(float4*)(a + 0) = *(const float4*)&As[kk][ty * 8 + 0];
            *(float4*)(a + 4) = *(const float4*)&As[kk][ty * 8 + 4];
            *(float4*)(b + 0) = *(const float4*)&Bs[kk][tx * 8 + 0];
            *(float4*)(b + 4) = *(const float4*)&Bs[kk][tx * 8 + 4];
            #pragma unroll
            for (int i = 0; i < 8; i++)
                #pragma unroll
                for (int j = 0; j < 8; j++)
                    acc[i][j] = fmaf(a[i], b[j], acc[i][j]);
        }
    }

    #pragma unroll
    for (int i = 0; i < 8; i++) {
        const int m = m0 + ty * 8 + i;
        float* crow = C + (size_t)m * N + n0 + tx * 8;
        *(float4*)(crow + 0) = make_float4(acc[i][0], acc[i][1], acc[i][2], acc[i][3]);
        *(float4*)(crow + 4) = make_float4(acc[i][4], acc[i][5], acc[i][6], acc[i][7]);
    }
}

// ---------------------------------------------------------------------------
// Row softmax over g_Scores: one block per row of length SS (2048).
// 256 threads, 8 elements/thread held in registers: one read + one write.
// ---------------------------------------------------------------------------
__global__ void __launch_bounds__(256) softmax_rows(float* __restrict__ Sc)
{
    const size_t row = blockIdx.x;
    float* p = Sc + row * (size_t)SS;
    const int tid = threadIdx.x;

    float v[8];
    float mx = -INFINITY;
    #pragma unroll
    for (int i = 0; i < 8; i++) {
        v[i] = p[tid + i * 256];
        mx = fmaxf(mx, v[i]);
    }

    __shared__ float red[256];
    red[tid] = mx;
    __syncthreads();
    #pragma unroll
    for (int s = 128; s > 0; s >>= 1) {
        if (tid < s) red[tid] = fmaxf(red[tid], red[tid + s]);
        __syncthreads();
    }
    mx = red[0];
    __syncthreads();

    float sum = 0.0f;
    #pragma unroll
    for (int i = 0; i < 8; i++) {
        v[i] = __expf(v[i] - mx);
        sum += v[i];
    }
    red[tid] = sum;
    __syncthreads();
    #pragma unroll
    for (int s = 128; s > 0; s >>= 1) {
        if (tid < s) red[tid] += red[tid + s];
        __syncthreads();
    }
    const float inv = 1.0f / red[0];

    #pragma unroll
    for (int i = 0; i < 8; i++)
        p[tid + i * 256] = v[i] * inv;
}

// ---------------------------------------------------------------------------
// Launch
// ---------------------------------------------------------------------------
extern "C" void kernel_launch(void* const* d_in, const int* in_sizes, int n_in,
                              void* d_out, int out_size)
{
    (void)in_sizes; (void)n_in; (void)out_size;
    const float* x  = (const float*)d_in[0];
    const float* Wq = (const float*)d_in[1];
    const float* bq = (const float*)d_in[2];
    const float* Wk = (const float*)d_in[3];
    const float* bk = (const float*)d_in[4];
    const float* Wv = (const float*)d_in[5];
    const float* bv = (const float*)d_in[6];
    const float* Wp = (const float*)d_in[7];
    const float* bp = (const float*)d_in[8];
    float* out = (float*)d_out;

    float *Q, *K, *V, *Sc, *O;
    cudaGetSymbolAddress((void**)&Q,  g_Q);
    cudaGetSymbolAddress((void**)&K,  g_K);
    cudaGetSymbolAddress((void**)&V,  g_V);
    cudaGetSymbolAddress((void**)&Sc, g_Scores);
    cudaGetSymbolAddress((void**)&O,  g_O);

    const float inv_sqrt_d = 1.0f / sqrtf((float)DD);

    // 1) Input projections: [16384,768] = x @ W^T + b
    {
        dim3 grid(DD / 128, NR / 128, 1);  // (6, 128)
        sgemm_nt<true><<<grid, 256>>>(x, Wq, Q, bq, NR, DD, DD, 1.0f, 0, 0, 0);
        sgemm_nt<true><<<grid, 256>>>(x, Wk, K, bk, NR, DD, DD, 1.0f, 0, 0, 0);
        sgemm_nt<true><<<grid, 256>>>(x, Wv, V, bv, NR, DD, DD, 1.0f, 0, 0, 0);
    }

    // 2) Scores = (Q @ K^T) / sqrt(D), per batch
    {
        dim3 grid(SS / 128, SS / 128, BB);  // (16, 16, 8)
        sgemm_nt<false><<<grid, 256>>>(Q, K, Sc, nullptr,
                                       SS, SS, DD, inv_sqrt_d,
                                       (size_t)SS * DD, (size_t)SS * DD,
                                       (size_t)SS * SS);
    }

    // 3) Row softmax
    softmax_rows<<<BB * SS, 256>>>(Sc);

    // 4) O = alpha @ V, per batch
    {
        dim3 grid(DD / 128, SS / 128, BB);  // (6, 16, 8)
        sgemm_nn<<<grid, 256>>>(Sc, V, O,
                                SS, DD, SS,
                                (size_t)SS * SS, (size_t)SS * DD,
                                (size_t)SS * DD);
    }

    // 5) Output projection -> d_out
    {
        dim3 grid(DD / 128, NR / 128, 1);
        sgemm_nt<true><<<grid, 256>>>(O, Wp, out, bp, NR, DD, DD, 1.0f, 0, 0, 0);
    }
}

// round 4
// speedup vs baseline: 2.3106x; 2.3106x over previous
#include <cuda_runtime.h>
#include <math.h>
#include <stdint.h>

// Problem constants
#define BB 8
#define SS 2048
#define DD 768
#define NR (BB * SS)   // 16384 rows

#define BM 128
#define BN 128
#define BK 16
#define PAD 8

// ---------------------------------------------------------------------------
// Scratch (allocation-free: __device__ globals per harness rules)
// ---------------------------------------------------------------------------
__device__ float g_Q[(size_t)NR * DD];
__device__ float g_K[(size_t)NR * DD];
__device__ float g_V[(size_t)NR * DD];
__device__ float g_Scores[(size_t)BB * SS * SS];
__device__ float g_O[(size_t)NR * DD];

// ---------------------------------------------------------------------------
// Helpers
// ---------------------------------------------------------------------------
__device__ __forceinline__ uint32_t f2tf32(float x) {
    uint32_t r;
    asm("cvt.rna.tf32.f32 %0, %1;" : "=r"(r) : "f"(x));
    return r;
}

__device__ __forceinline__ void mma_tf32(float* d, const uint32_t* a,
                                         const uint32_t* b) {
    asm volatile(
        "mma.sync.aligned.m16n8k8.row.col.f32.tf32.tf32.f32 "
        "{%0,%1,%2,%3}, {%4,%5,%6,%7}, {%8,%9}, {%0,%1,%2,%3};\n"
        : "+f"(d[0]), "+f"(d[1]), "+f"(d[2]), "+f"(d[3])
        : "r"(a[0]), "r"(a[1]), "r"(a[2]), "r"(a[3]),
          "r"(b[0]), "r"(b[1]));
}

// ---------------------------------------------------------------------------
// TF32 tensor-core GEMM.
//   TRANS_B=true : C = scale*(A @ B^T) + bias   A:[M,K], B:[N,K]  (NT)
//   TRANS_B=false: C = scale*(A @ B)   + bias   A:[M,K], B:[K,N]  (NN)
// 128x128x16 tile, 256 threads, 8 warps (2 M x 4 N), warp tile 64x32.
// Requires M%128==0, N%128==0, K%16==0.
// ---------------------------------------------------------------------------
template <bool TRANS_B, bool HAS_BIAS>
__global__ void __launch_bounds__(256) mma_gemm(
    const float* __restrict__ A, const float* __restrict__ B,
    float* __restrict__ C, const float* __restrict__ bias,
    int M, int N, int K, float scale,
    size_t sA, size_t sB, size_t sC)
{
    A += (size_t)blockIdx.z * sA;
    B += (size_t)blockIdx.z * sB;
    C += (size_t)blockIdx.z * sC;

    __shared__ uint32_t As[2][BK][BM + PAD];   // k-major: As[k][m]
    __shared__ uint32_t Bs[2][BK][BN + PAD];   // k-major: Bs[k][n]

    const int tid = threadIdx.x;
    const int wid = tid >> 5;
    const int lane = tid & 31;
    const int gid = lane >> 2;   // 0..7
    const int tig = lane & 3;    // 0..3

    const int wm_base = (wid >> 2) * 64;   // 0 or 64
    const int wn_base = (wid & 3) * 32;    // 0,32,64,96

    const int m0 = blockIdx.y * BM;
    const int n0 = blockIdx.x * BN;

    // A loader (always [M,K] row-major, transposed into As[k][m])
    const int lr = tid >> 1;          // 0..127
    const int lk = (tid & 1) * 8;     // 0 or 8
    const float* Aptr = A + (size_t)(m0 + lr) * K + lk;

    // B loaders
    const float* BptrT = B + (size_t)(n0 + lr) * K + lk;               // NT
    const int bro = (tid * 2) >> 5;          // 0..15 (k row within tile)
    const int bco = ((tid * 2) & 31) * 4;    // 0..120 step 8
    const float* BptrN = B + (size_t)bro * N + n0 + bco;               // NN

    float acc[4][4][4];
    #pragma unroll
    for (int mi = 0; mi < 4; mi++)
        #pragma unroll
        for (int ni = 0; ni < 4; ni++)
            #pragma unroll
            for (int r = 0; r < 4; r++) acc[mi][ni][r] = 0.0f;

    float4 av0, av1, bv0, bv1;

    // ---- prologue: tile 0 -> buf 0
    av0 = *(const float4*)(Aptr + 0);
    av1 = *(const float4*)(Aptr + 4);
    if (TRANS_B) {
        bv0 = *(const float4*)(BptrT + 0);
        bv1 = *(const float4*)(BptrT + 4);
    } else {
        bv0 = *(const float4*)(BptrN + 0);
        bv1 = *(const float4*)(BptrN + 4);
    }
    {
        const float a0[8] = {av0.x, av0.y, av0.z, av0.w, av1.x, av1.y, av1.z, av1.w};
        #pragma unroll
        for (int j = 0; j < 8; j++) As[0][lk + j][lr] = f2tf32(a0[j]);
        const float b0[8] = {bv0.x, bv0.y, bv0.z, bv0.w, bv1.x, bv1.y, bv1.z, bv1.w};
        if (TRANS_B) {
            #pragma unroll
            for (int j = 0; j < 8; j++) Bs[0][lk + j][lr] = f2tf32(b0[j]);
        } else {
            #pragma unroll
            for (int j = 0; j < 8; j++) Bs[0][bro][bco + j] = f2tf32(b0[j]);
        }
    }
    __syncthreads();

    int buf = 0;
    for (int k0 = 0; k0 < K; k0 += BK) {
        const bool has_next = (k0 + BK) < K;
        if (has_next) {
            av0 = *(const float4*)(Aptr + k0 + BK);
            av1 = *(const float4*)(Aptr + k0 + BK + 4);
            if (TRANS_B) {
                bv0 = *(const float4*)(BptrT + k0 + BK);
                bv1 = *(const float4*)(BptrT + k0 + BK + 4);
            } else {
                bv0 = *(const float4*)(BptrN + (size_t)(k0 + BK) * N);
                bv1 = *(const float4*)(BptrN + (size_t)(k0 + BK) * N + 4);
            }
        }

        // ---- compute current buffer
        #pragma unroll
        for (int ks = 0; ks < 2; ks++) {
            const int kb = ks * 8;
            uint32_t af[4][4], bf[4][2];
            #pragma unroll
            for (int mi = 0; mi < 4; mi++) {
                const int m = wm_base + mi * 16 + gid;
                af[mi][0] = As[buf][kb + tig][m];
                af[mi][1] = As[buf][kb + tig][m + 8];
                af[mi][2] = As[buf][kb + tig + 4][m];
                af[mi][3] = As[buf][kb + tig + 4][m + 8];
            }
            #pragma unroll
            for (int ni = 0; ni < 4; ni++) {
                const int n = wn_base + ni * 8 + gid;
                bf[ni][0] = Bs[buf][kb + tig][n];
                bf[ni][1] = Bs[buf][kb + tig + 4][n];
            }
            #pragma unroll
            for (int mi = 0; mi < 4; mi++)
                #pragma unroll
                for (int ni = 0; ni < 4; ni++)
                    mma_tf32(acc[mi][ni], af[mi], bf[ni]);
        }

        if (has_next) {
            __syncthreads();
            const int nb = buf ^ 1;
            const float a0[8] = {av0.x, av0.y, av0.z, av0.w, av1.x, av1.y, av1.z, av1.w};
            #pragma unroll
            for (int j = 0; j < 8; j++) As[nb][lk + j][lr] = f2tf32(a0[j]);
            const float b0[8] = {bv0.x, bv0.y, bv0.z, bv0.w, bv1.x, bv1.y, bv1.z, bv1.w};
            if (TRANS_B) {
                #pragma unroll
                for (int j = 0; j < 8; j++) Bs[nb][lk + j][lr] = f2tf32(b0[j]);
            } else {
                #pragma unroll
                for (int j = 0; j < 8; j++) Bs[nb][bro][bco + j] = f2tf32(b0[j]);
            }
            __syncthreads();
            buf = nb;
        }
    }

    // ---- epilogue
    #pragma unroll
    for (int ni = 0; ni < 4; ni++) {
        const int col = n0 + wn_base + ni * 8 + tig * 2;
        float b0 = 0.0f, b1 = 0.0f;
        if (HAS_BIAS) { b0 = bias[col]; b1 = bias[col + 1]; }
        #pragma unroll
        for (int mi = 0; mi < 4; mi++) {
            const int row = m0 + wm_base + mi * 16 + gid;
            const float* c = acc[mi][ni];
            float2 v0 = make_float2(c[0] * scale + b0, c[1] * scale + b1);
            float2 v1 = make_float2(c[2] * scale + b0, c[3] * scale + b1);
            *(float2*)(C + (size_t)row * N + col) = v0;
            *(float2*)(C + (size_t)(row + 8) * N + col) = v1;
        }
    }
}

// ---------------------------------------------------------------------------
// Row softmax: one block per row of length SS (2048), 256 threads.
// ---------------------------------------------------------------------------
__global__ void __launch_bounds__(256) softmax_rows(float* __restrict__ Sc)
{
    const size_t row = blockIdx.x;
    float* p = Sc + row * (size_t)SS;
    const int tid = threadIdx.x;

    float v[8];
    float mx = -INFINITY;
    #pragma unroll
    for (int i = 0; i < 8; i++) {
        v[i] = p[tid + i * 256];
        mx = fmaxf(mx, v[i]);
    }

    __shared__ float red[256];
    red[tid] = mx;
    __syncthreads();
    #pragma unroll
    for (int s = 128; s > 0; s >>= 1) {
        if (tid < s) red[tid] = fmaxf(red[tid], red[tid + s]);
        __syncthreads();
    }
    mx = red[0];
    __syncthreads();

    float sum = 0.0f;
    #pragma unroll
    for (int i = 0; i < 8; i++) {
        v[i] = __expf(v[i] - mx);
        sum += v[i];
    }
    red[tid] = sum;
    __syncthreads();
    #pragma unroll
    for (int s = 128; s > 0; s >>= 1) {
        if (tid < s) red[tid] += red[tid + s];
        __syncthreads();
    }
    const float inv = 1.0f / red[0];

    #pragma unroll
    for (int i = 0; i < 8; i++)
        p[tid + i * 256] = v[i] * inv;
}

// ---------------------------------------------------------------------------
// Launch
// ---------------------------------------------------------------------------
extern "C" void kernel_launch(void* const* d_in, const int* in_sizes, int n_in,
                              void* d_out, int out_size)
{
    (void)in_sizes; (void)n_in; (void)out_size;
    const float* x  = (const float*)d_in[0];
    const float* Wq = (const float*)d_in[1];
    const float* bq = (const float*)d_in[2];
    const float* Wk = (const float*)d_in[3];
    const float* bk = (const float*)d_in[4];
    const float* Wv = (const float*)d_in[5];
    const float* bv = (const float*)d_in[6];
    const float* Wp = (const float*)d_in[7];
    const float* bp = (const float*)d_in[8];
    float* out = (float*)d_out;

    float *Q, *K, *V, *Sc, *O;
    cudaGetSymbolAddress((void**)&Q,  g_Q);
    cudaGetSymbolAddress((void**)&K,  g_K);
    cudaGetSymbolAddress((void**)&V,  g_V);
    cudaGetSymbolAddress((void**)&Sc, g_Scores);
    cudaGetSymbolAddress((void**)&O,  g_O);

    const float inv_sqrt_d = 1.0f / sqrtf((float)DD);

    // 1) Input projections: [16384,768] = x @ W^T + b  (NT + bias)
    {
        dim3 grid(DD / BN, NR / BM, 1);  // (6, 128)
        mma_gemm<true, true><<<grid, 256>>>(x, Wq, Q, bq, NR, DD, DD, 1.0f, 0, 0, 0);
        mma_gemm<true, true><<<grid, 256>>>(x, Wk, K, bk, NR, DD, DD, 1.0f, 0, 0, 0);
        mma_gemm<true, true><<<grid, 256>>>(x, Wv, V, bv, NR, DD, DD, 1.0f, 0, 0, 0);
    }

    // 2) Scores = (Q @ K^T) / sqrt(D), per batch  (NT, scaled)
    {
        dim3 grid(SS / BN, SS / BM, BB);  // (16, 16, 8)
        mma_gemm<true, false><<<grid, 256>>>(Q, K, Sc, nullptr,
                                             SS, SS, DD, inv_sqrt_d,
                                             (size_t)SS * DD, (size_t)SS * DD,
                                             (size_t)SS * SS);
    }

    // 3) Row softmax
    softmax_rows<<<BB * SS, 256>>>(Sc);

    // 4) O = alpha @ V, per batch  (NN)
    {
        dim3 grid(DD / BN, SS / BM, BB);  // (6, 16, 8)
        mma_gemm<false, false><<<grid, 256>>>(Sc, V, O, nullptr,
                                              SS, DD, SS, 1.0f,
                                              (size_t)SS * SS, (size_t)SS * DD,
                                              (size_t)SS * DD);
    }

    // 5) Output projection -> d_out (NT + bias)
    {
        dim3 grid(DD / BN, NR / BM, 1);
        mma_gemm<true, true><<<grid, 256>>>(O, Wp, out, bp, NR, DD, DD, 1.0f, 0, 0, 0);
    }
}

// round 7
// speedup vs baseline: 2.7234x; 1.1786x over previous
#include <cuda_runtime.h>
#include <math.h>
#include <stdint.h>

// Problem constants
#define BB 8
#define SS 2048
#define DD 768
#define NR (BB * SS)   // 16384 rows

#define BM 128
#define BN 128
#define BK 16
#define LPAD 4   // row stride BK+4=20 words -> conflict-free ldmatrix
#define NPAD 8   // NN k-major B tile pad

// ---------------------------------------------------------------------------
// Scratch (allocation-free: __device__ globals per harness rules)
// ---------------------------------------------------------------------------
__device__ float g_Q[(size_t)NR * DD];
__device__ float g_K[(size_t)NR * DD];
__device__ float g_V[(size_t)NR * DD];
__device__ float g_Scores[(size_t)BB * SS * SS];
__device__ float g_O[(size_t)NR * DD];

// ---------------------------------------------------------------------------
// Helpers
// ---------------------------------------------------------------------------
__device__ __forceinline__ uint32_t f2tf32(float x) {
    uint32_t r;
    asm("cvt.rna.tf32.f32 %0, %1;" : "=r"(r) : "f"(x));
    return r;
}

__device__ __forceinline__ void mma_tf32(float* d, const uint32_t* a,
                                         const uint32_t* b) {
    asm volatile(
        "mma.sync.aligned.m16n8k8.row.col.f32.tf32.tf32.f32 "
        "{%0,%1,%2,%3}, {%4,%5,%6,%7}, {%8,%9}, {%0,%1,%2,%3};\n"
        : "+f"(d[0]), "+f"(d[1]), "+f"(d[2]), "+f"(d[3])
        : "r"(a[0]), "r"(a[1]), "r"(a[2]), "r"(a[3]),
          "r"(b[0]), "r"(b[1]));
}

__device__ __forceinline__ void ldsm_x4(uint32_t* r, uint32_t addr) {
    asm volatile(
        "ldmatrix.sync.aligned.m8n8.x4.shared.b16 {%0,%1,%2,%3}, [%4];"
        : "=r"(r[0]), "=r"(r[1]), "=r"(r[2]), "=r"(r[3])
        : "r"(addr));
}

__device__ __forceinline__ void ldsm_x2(uint32_t* r, uint32_t addr) {
    asm volatile(
        "ldmatrix.sync.aligned.m8n8.x2.shared.b16 {%0,%1}, [%2];"
        : "=r"(r[0]), "=r"(r[1])
        : "r"(addr));
}

__device__ __forceinline__ uint32_t smem_u32(const void* p) {
    return (uint32_t)__cvta_generic_to_shared(p);
}

// ---------------------------------------------------------------------------
// TF32 tensor-core GEMM with ldmatrix fragment loads.
//   TRANS_B=true : C = scale*(A @ B^T) + bias   A:[M,K], B:[N,K]  (NT)
//   TRANS_B=false: C = scale*(A @ B)   + bias   A:[M,K], B:[K,N]  (NN)
// 128x128x16 tile, 256 threads, 8 warps (2 M x 4 N), warp tile 64x32.
// A (and B for NT) stored row-major [row][BK+LPAD]; fragments via ldmatrix.
// B for NN stored k-major [BK][BN+NPAD]; fragments via scalar LDS.
// ---------------------------------------------------------------------------
template <bool TRANS_B, bool HAS_BIAS>
__global__ void __launch_bounds__(256, 2) mma_gemm(
    const float* __restrict__ A, const float* __restrict__ B,
    float* __restrict__ C, const float* __restrict__ bias,
    int M, int N, int K, float scale,
    size_t sA, size_t sB, size_t sC)
{
    A += (size_t)blockIdx.z * sA;
    B += (size_t)blockIdx.z * sB;
    C += (size_t)blockIdx.z * sC;

    __shared__ uint32_t As[2][BM][BK + LPAD];
    __shared__ uint32_t Bs[2][TRANS_B ? BN : BK][TRANS_B ? (BK + LPAD) : (BN + NPAD)];

    const int tid = threadIdx.x;
    const int wid = tid >> 5;
    const int lane = tid & 31;
    const int gid = lane >> 2;   // 0..7
    const int tig = lane & 3;    // 0..3

    const int wm_base = (wid >> 2) * 64;   // 0 or 64
    const int wn_base = (wid & 3) * 32;    // 0,32,64,96

    const int m0 = blockIdx.y * BM;
    const int n0 = blockIdx.x * BN;

    // A loader: thread -> row lr, k cols [lk, lk+8)
    const int lr = tid >> 1;
    const int lk = (tid & 1) * 8;
    const float* Aptr = A + (size_t)(m0 + lr) * K + lk;
    const float* BptrT = B + (size_t)(n0 + lr) * K + lk;            // NT
    const int bro = tid >> 4;              // 0..15
    const int bco = (tid & 15) * 8;        // 0..120
    const float* BptrN = B + (size_t)bro * N + n0 + bco;            // NN

    // ldmatrix per-lane source coordinates
    const int a_row = lane & 15;           // row within 16-row fragment
    const int a_coff = (lane >> 4) * 4;    // k sub-offset 0 or 4
    const int b_row = lane & 7;            // NT B: row within 8-row fragment
    const int b_coff = ((lane >> 3) & 1) * 4;

    float acc[4][4][4];
    #pragma unroll
    for (int mi = 0; mi < 4; mi++)
        #pragma unroll
        for (int ni = 0; ni < 4; ni++)
            #pragma unroll
            for (int r = 0; r < 4; r++) acc[mi][ni][r] = 0.0f;

    float4 av0, av1, bv0, bv1;

    auto stage = [&](int nb) {
        // A: convert + two STS.128
        uint4 aw0, aw1;
        aw0.x = f2tf32(av0.x); aw0.y = f2tf32(av0.y);
        aw0.z = f2tf32(av0.z); aw0.w = f2tf32(av0.w);
        aw1.x = f2tf32(av1.x); aw1.y = f2tf32(av1.y);
        aw1.z = f2tf32(av1.z); aw1.w = f2tf32(av1.w);
        *(uint4*)&As[nb][lr][lk]     = aw0;
        *(uint4*)&As[nb][lr][lk + 4] = aw1;
        uint4 bw0, bw1;
        bw0.x = f2tf32(bv0.x); bw0.y = f2tf32(bv0.y);
        bw0.z = f2tf32(bv0.z); bw0.w = f2tf32(bv0.w);
        bw1.x = f2tf32(bv1.x); bw1.y = f2tf32(bv1.y);
        bw1.z = f2tf32(bv1.z); bw1.w = f2tf32(bv1.w);
        if (TRANS_B) {
            *(uint4*)&Bs[nb][lr][lk]     = bw0;
            *(uint4*)&Bs[nb][lr][lk + 4] = bw1;
        } else {
            // transpose-free k-major store: row bro, cols bco..bco+7
            *(uint4*)&Bs[nb][bro][bco]     = bw0;
            *(uint4*)&Bs[nb][bro][bco + 4] = bw1;
        }
    };

    // ---- prologue: tile 0 -> buf 0
    av0 = *(const float4*)(Aptr + 0);
    av1 = *(const float4*)(Aptr + 4);
    if (TRANS_B) {
        bv0 = *(const float4*)(BptrT + 0);
        bv1 = *(const float4*)(BptrT + 4);
    } else {
        bv0 = *(const float4*)(BptrN + 0);
        bv1 = *(const float4*)(BptrN + 4);
    }
    stage(0);
    __syncthreads();

    int buf = 0;
    for (int k0 = 0; k0 < K; k0 += BK) {
        const bool has_next = (k0 + BK) < K;
        if (has_next) {
            av0 = *(const float4*)(Aptr + k0 + BK);
            av1 = *(const float4*)(Aptr + k0 + BK + 4);
            if (TRANS_B) {
                bv0 = *(const float4*)(BptrT + k0 + BK);
                bv1 = *(const float4*)(BptrT + k0 + BK + 4);
            } else {
                // NN: next tile rows are k0+BK+bro; same column window
                const float* p = BptrN + (size_t)(k0 + BK) * N;
                bv0 = *(const float4*)(p + 0);
                bv1 = *(const float4*)(p + 4);
            }
        }

        // ---- compute current buffer
        #pragma unroll
        for (int ks = 0; ks < 2; ks++) {
            const int kb = ks * 8;
            uint32_t af[4][4], bf[4][2];
            #pragma unroll
            for (int mi = 0; mi < 4; mi++) {
                uint32_t addr = smem_u32(&As[buf][wm_base + mi * 16 + a_row][kb + a_coff]);
                ldsm_x4(af[mi], addr);
            }
            if (TRANS_B) {
                #pragma unroll
                for (int ni = 0; ni < 4; ni++) {
                    uint32_t addr = smem_u32(&Bs[buf][wn_base + ni * 8 + b_row][kb + b_coff]);
                    ldsm_x2(bf[ni], addr);
                }
            } else {
                #pragma unroll
                for (int ni = 0; ni < 4; ni++) {
                    const int n = wn_base + ni * 8 + gid;
                    bf[ni][0] = Bs[buf][kb + tig][n];
                    bf[ni][1] = Bs[buf][kb + tig + 4][n];
                }
            }
            #pragma unroll
            for (int mi = 0; mi < 4; mi++)
                #pragma unroll
                for (int ni = 0; ni < 4; ni++)
                    mma_tf32(acc[mi][ni], af[mi], bf[ni]);
        }

        if (has_next) {
            __syncthreads();
            stage(buf ^ 1);
            __syncthreads();
            buf ^= 1;
        }
    }

    // ---- epilogue
    #pragma unroll
    for (int ni = 0; ni < 4; ni++) {
        const int col = n0 + wn_base + ni * 8 + tig * 2;
        float b0 = 0.0f, b1 = 0.0f;
        if (HAS_BIAS) { b0 = bias[col]; b1 = bias[col + 1]; }
        #pragma unroll
        for (int mi = 0; mi < 4; mi++) {
            const int row = m0 + wm_base + mi * 16 + gid;
            const float* c = acc[mi][ni];
            float2 v0 = make_float2(c[0] * scale + b0, c[1] * scale + b1);
            float2 v1 = make_float2(c[2] * scale + b0, c[3] * scale + b1);
            *(float2*)(C + (size_t)row * N + col) = v0;
            *(float2*)(C + (size_t)(row + 8) * N + col) = v1;
        }
    }
}

// ---------------------------------------------------------------------------
// Row softmax: one block per row of length SS (2048), 256 threads.
// ---------------------------------------------------------------------------
__global__ void __launch_bounds__(256) softmax_rows(float* __restrict__ Sc)
{
    const size_t row = blockIdx.x;
    float* p = Sc + row * (size_t)SS;
    const int tid = threadIdx.x;

    float v[8];
    float mx = -INFINITY;
    #pragma unroll
    for (int i = 0; i < 8; i++) {
        v[i] = p[tid + i * 256];
        mx = fmaxf(mx, v[i]);
    }

    __shared__ float red[256];
    red[tid] = mx;
    __syncthreads();
    #pragma unroll
    for (int s = 128; s > 0; s >>= 1) {
        if (tid < s) red[tid] = fmaxf(red[tid], red[tid + s]);
        __syncthreads();
    }
    mx = red[0];
    __syncthreads();

    float sum = 0.0f;
    #pragma unroll
    for (int i = 0; i < 8; i++) {
        v[i] = __expf(v[i] - mx);
        sum += v[i];
    }
    red[tid] = sum;
    __syncthreads();
    #pragma unroll
    for (int s = 128; s > 0; s >>= 1) {
        if (tid < s) red[tid] += red[tid + s];
        __syncthreads();
    }
    const float inv = 1.0f / red[0];

    #pragma unroll
    for (int i = 0; i < 8; i++)
        p[tid + i * 256] = v[i] * inv;
}

// ---------------------------------------------------------------------------
// Launch
// ---------------------------------------------------------------------------
extern "C" void kernel_launch(void* const* d_in, const int* in_sizes, int n_in,
                              void* d_out, int out_size)
{
    (void)in_sizes; (void)n_in; (void)out_size;
    const float* x  = (const float*)d_in[0];
    const float* Wq = (const float*)d_in[1];
    const float* bq = (const float*)d_in[2];
    const float* Wk = (const float*)d_in[3];
    const float* bk = (const float*)d_in[4];
    const float* Wv = (const float*)d_in[5];
    const float* bv = (const float*)d_in[6];
    const float* Wp = (const float*)d_in[7];
    const float* bp = (const float*)d_in[8];
    float* out = (float*)d_out;

    float *Q, *K, *V, *Sc, *O;
    cudaGetSymbolAddress((void**)&Q,  g_Q);
    cudaGetSymbolAddress((void**)&K,  g_K);
    cudaGetSymbolAddress((void**)&V,  g_V);
    cudaGetSymbolAddress((void**)&Sc, g_Scores);
    cudaGetSymbolAddress((void**)&O,  g_O);

    const float inv_sqrt_d = 1.0f / sqrtf((float)DD);

    // 1) Input projections: [16384,768] = x @ W^T + b  (NT + bias)
    {
        dim3 grid(DD / BN, NR / BM, 1);  // (6, 128)
        mma_gemm<true, true><<<grid, 256>>>(x, Wq, Q, bq, NR, DD, DD, 1.0f, 0, 0, 0);
        mma_gemm<true, true><<<grid, 256>>>(x, Wk, K, bk, NR, DD, DD, 1.0f, 0, 0, 0);
        mma_gemm<true, true><<<grid, 256>>>(x, Wv, V, bv, NR, DD, DD, 1.0f, 0, 0, 0);
    }

    // 2) Scores = (Q @ K^T) / sqrt(D), per batch  (NT, scaled)
    {
        dim3 grid(SS / BN, SS / BM, BB);  // (16, 16, 8)
        mma_gemm<true, false><<<grid, 256>>>(Q, K, Sc, nullptr,
                                             SS, SS, DD, inv_sqrt_d,
                                             (size_t)SS * DD, (size_t)SS * DD,
                                             (size_t)SS * SS);
    }

    // 3) Row softmax
    softmax_rows<<<BB * SS, 256>>>(Sc);

    // 4) O = alpha @ V, per batch  (NN)
    {
        dim3 grid(DD / BN, SS / BM, BB);  // (6, 16, 8)
        mma_gemm<false, false><<<grid, 256>>>(Sc, V, O, nullptr,
                                              SS, DD, SS, 1.0f,
                                              (size_t)SS * SS, (size_t)SS * DD,
                                              (size_t)SS * DD);
    }

    // 5) Output projection -> d_out (NT + bias)
    {
        dim3 grid(DD / BN, NR / BM, 1);
        mma_gemm<true, true><<<grid, 256>>>(O, Wp, out, bp, NR, DD, DD, 1.0f, 0, 0, 0);
    }
}